// round 8
// baseline (speedup 1.0000x reference)
#include <cuda_runtime.h>

// Problem constants (fixed by the reference)
#define Nn    1000
#define INF_  32
#define Hh    128
#define Mm    128
#define DEGk  16
#define Pp    2
#define OUTn  10
#define MAXD  (10 * Nn)                 // dequeue budget = queue slots ever read
#define NSMAX 64
#define MAXMSG (NSMAX + MAXD)           // distinct messages ever created
#define THR   (1.0f - 1e-7f)

// Persistent device state (static allocation — no cudaMalloc allowed)
__device__ float g_feats[Nn * Hh];
__device__ float g_final[Nn * Hh];
__device__ float g_actf[Nn];
__device__ float g_msgs[(size_t)MAXMSG * Mm];   // dedup'd message store (~5.2 MB)

// ---- packed f32x2 helpers (sm_103a) ---------------------------------------
__device__ __forceinline__ unsigned long long fma2(unsigned long long a,
                                                   unsigned long long b,
                                                   unsigned long long c)
{
    unsigned long long d;
    asm("fma.rn.f32x2 %0, %1, %2, %3;" : "=l"(d) : "l"(a), "l"(b), "l"(c));
    return d;
}
__device__ __forceinline__ unsigned long long pack2(float lo, float hi)
{
    unsigned long long d;
    asm("mov.b64 %0, {%1, %2};" : "=l"(d) : "f"(lo), "f"(hi));
    return d;
}
__device__ __forceinline__ void unpack2(unsigned long long v, float& lo, float& hi)
{
    asm("mov.b64 {%0, %1}, %2;" : "=f"(lo), "=f"(hi) : "l"(v));
}

// ---------------------------------------------------------------------------
// Kernel 1: encoder + state init + seed messages + actf seed. grid = Nn x 128
// ---------------------------------------------------------------------------
__global__ void k_init(const float* __restrict__ xa,
                       const float* __restrict__ fmsg,
                       const int*  nstart_p,
                       const float* __restrict__ enc_w,
                       const float* __restrict__ enc_b,
                       const float* __restrict__ act_w)
{
    int n = blockIdx.x, t = threadIdx.x;
    int lane = t & 31;
    __shared__ float sx[INF_];
    __shared__ float sw[4];
    if (t < INF_) sx[t] = xa[n * INF_ + t];
    __syncthreads();

    float acc = enc_b[t];
#pragma unroll
    for (int k = 0; k < INF_; k++) acc += sx[k] * enc_w[k * Hh + t];

    g_feats[n * Hh + t] = acc;
    g_final[n * Hh + t] = 0.0f;

    // actf seed: enc_out . act_w[0:128]
    float pa = acc * act_w[t];
#pragma unroll
    for (int o = 16; o; o >>= 1) pa += __shfl_xor_sync(0xffffffffu, pa, o);
    if (lane == 0) sw[t >> 5] = pa;
    __syncthreads();
    if (t == 0) g_actf[n] = sw[0] + sw[1] + sw[2] + sw[3];

    int ns = nstart_p ? *nstart_p : NSMAX;
    if (n < ns) g_msgs[(size_t)n * Mm + t] = fmsg[n * Mm + t];
}

// ---- warp-uniform ballot skip-scan with optional tact substitution --------
__device__ __forceinline__ void scan_q(const int* __restrict__ s_qpack,
                                       const float* __restrict__ s_tact,
                                       int p_start, int limit, int lane,
                                       int subn, float subv,
                                       int& found, int& fpos, int& fpk, float& fta)
{
    const unsigned FULL = 0xffffffffu;
    int p = p_start + lane;
    found = 0; fpos = 0; fpk = 0; fta = 0.0f;
    while (true) {
        bool  valid = (p < limit);
        int   pk    = valid ? s_qpack[p] : 0;
        int   nd    = pk & 1023;
        float tv;
        if (valid) tv = (nd == subn) ? subv : s_tact[nd];
        else       tv = 2.0f;
        unsigned ok = __ballot_sync(FULL, valid && (tv <= THR));
        if (ok) {
            int f = __ffs((int)ok) - 1;
            fpos  = (p - lane) + f;
            fpk   = __shfl_sync(FULL, pk, f);
            fta   = __shfl_sync(FULL, tv, f);
            found = 1;
            return;
        }
        if (__ballot_sync(FULL, valid) != FULL) return;
        p += 32;
    }
}

// ---------------------------------------------------------------------------
// Kernel 2: sequential queue simulation. ONE block, 512 threads (16 warps).
//  * queue + tact + actf caches in SMEM; msg-half weights in SMEM
//  * hit-path weights register-resident (fma.rn.f32x2), warp-local reduce
//  * EXACT next-entry scan at gate time (na known -> tact substitution),
//    prefetch LDGs issued there; same-node case copies ys / recomputed final
//  * s_wtmp double-buffered (parity) -> no cross-phase race
//  * 2 barriers per hit step
// ---------------------------------------------------------------------------
__global__ void __launch_bounds__(512, 1) k_main(
    const int*  __restrict__ neighbors,
    const int*  nstart_p,
    const float* __restrict__ ns_w, const float* __restrict__ ns_b,
    const float* __restrict__ nm_w, const float* __restrict__ nm_b,
    const float* __restrict__ act_w, const float* __restrict__ act_b)
{
    extern __shared__ __align__(16) float dyn[];
    float* s_mwA  = dyn;                      // ns_w rows 128..255 (64 KB)
    float* s_mwB  = dyn + 128 * 128;          // nm_w rows 128..255 (64 KB)
    int*   s_qpack = (int*)(dyn + 2 * 128 * 128);   // packed queue (40 KB)

    __shared__ float s_tact[Nn];                    // 4 KB
    __shared__ float s_actf[Nn];                    // 4 KB
    __shared__ __align__(16) float xs[128];         // feats[node] (prefetched)
    __shared__ __align__(16) float ys[128];         // ns output (relu)
    __shared__ __align__(16) float s_fin[128];      // g_final[node] (prefetched)
    __shared__ float s_msg[128];
    __shared__ float s_nsmsg[128], s_nmmsg[128];    // cached msg-half partials
    __shared__ __align__(16) float sredA[8 * 128];
    __shared__ __align__(16) float sredB[8 * 128];
    __shared__ float s_actw[256];
    __shared__ float s_nsb[128], s_nmb[128];
    __shared__ __align__(16) float s_wtmp[2][16];   // actf partials, double-buffered
    __shared__ float s_wactm[4];
    __shared__ float s_actmsg;
    __shared__ int   s_next[4];                     // {pos, pk, ta_bits, found}

    const int t    = threadIdx.x;
    const int lane = t & 31;
    const int warp = t >> 5;
    const unsigned FULL = 0xffffffffu;

    if (t < 256) s_actw[t] = act_w[t];
    if (t < 128) { s_nsb[t] = ns_b[t]; s_nmb[t] = nm_b[t]; }
    if (t < 32)  s_wtmp[t >> 4][t & 15] = 0.0f;
    if (t == 0)  s_actmsg = 0.0f;
    const float actb = act_b[0];

    for (int i = t; i < Nn; i += 512) { s_tact[i] = 0.0f; s_actf[i] = g_actf[i]; }

    const int ns0 = nstart_p ? *nstart_p : NSMAX;
    for (int i = t; i < ns0; i += 512) s_qpack[i] = (i << 10) | i;  // mid=i,node=i

    // msg-half weights into SMEM (rows 128..255 of both matrices)
    {
        const float4* a4 = (const float4*)(ns_w + 128 * Hh);
        const float4* b4 = (const float4*)(nm_w + 128 * Hh);
        for (int i = t; i < 128 * 32; i += 512) {
            ((float4*)s_mwA)[i] = a4[i];
            ((float4*)s_mwB)[i] = b4[i];
        }
    }

    // hit-path weights into registers (k-pair packed)
    const int o = (warp << 3) + (lane & 7);     // output column owned
    const int c = lane >> 3;                    // k-chunk (0..3)
    unsigned long long wA[16], wB[16];
#pragma unroll
    for (int kk = 0; kk < 16; kk++) {
        int k = c * 32 + 2 * kk;
        wA[kk] = pack2(ns_w[k * Hh + o], ns_w[(k + 1) * Hh + o]);
        wB[kk] = pack2(nm_w[k * Hh + o], nm_w[(k + 1) * Hh + o]);
    }

    int head = 0, tail = ns0, nproc = 0;
    int last_mid = -1, node_prev = -1;
    int have = 0, pos = 0, pk = 0; float ta = 0.0f;
    int pp = 0;                                     // s_wtmp read-parity
    __syncthreads();

    while (true) {
        const int limit = (tail < MAXD) ? tail : MAXD;

        if (!have) {
            head = pos;                   // resume point stored by gate on failure
            if (head >= limit) break;
            int f, fp, fk; float ft;
            scan_q(s_qpack, s_tact, head, limit, lane, -1, 0.0f, f, fp, fk, ft);
            if (!f) break;
            pos = fp; pk = fk; ta = ft;
            int cn = pk & 1023, cm = pk >> 10;
            if (t < 128) {
                xs[t]    = g_feats[cn * Hh + t];
                s_fin[t] = g_final[cn * Hh + t];
                if (cm != last_mid) s_msg[t] = g_msgs[(size_t)cm * Mm + t];
            }
            __syncthreads();
            have = 1;
        }

        const int node = pk & 1023;
        const int mid  = pk >> 10;

        // neighbors LDG early (warp 4) — consumed in phase 3
        int mynb = 0;
        if (warp == 4 && lane < DEGk) mynb = neighbors[node * DEGk + lane];

        // ---- miss path: msg-half partials for this mid (SMEM weights) ----
        if (mid != last_mid) {
            if (warp < 4) {                       // act msg-half partial
                float pa = s_msg[t] * s_actw[128 + t];
#pragma unroll
                for (int oo = 16; oo; oo >>= 1)
                    pa += __shfl_xor_sync(FULL, pa, oo);
                if (lane == 0) s_wactm[warp] = pa;
            }
            {
                const float4* w4p = (warp < 8) ? (const float4*)s_mwA
                                               : (const float4*)s_mwB;
                float* red = (warp < 8) ? sredA : sredB;
                int wl = warp & 7, kb = (warp & 7) * 16;
                float4 a = make_float4(0.f, 0.f, 0.f, 0.f);
#pragma unroll 8
                for (int kk = 0; kk < 16; kk++) {
                    float  mk = s_msg[kb + kk];
                    float4 w4 = w4p[(kb + kk) * 32 + lane];
                    a.x += mk * w4.x; a.y += mk * w4.y;
                    a.z += mk * w4.z; a.w += mk * w4.w;
                }
                ((float4*)red)[wl * 32 + lane] = a;
            }
            __syncthreads();
            if (t < 128) {
                float sa = 0.f, sb = 0.f;
#pragma unroll
                for (int j = 0; j < 8; j++) {
                    sa += sredA[j * 128 + t];
                    sb += sredB[j * 128 + t];
                }
                s_nsmsg[t] = sa; s_nmmsg[t] = sb;
            }
            if (t == 0)
                s_actmsg = s_wactm[0] + s_wactm[1] + s_wactm[2] + s_wactm[3];
            __syncthreads();
            last_mid = mid;
        }

        // ---- ACT gate (all threads; read parity buffer pp — race-free) ----
        float wsum;
        {
            const float4* wt4 = (const float4*)s_wtmp[pp];
            float4 w0 = wt4[0], w1 = wt4[1], w2 = wt4[2], w3 = wt4[3];
            wsum = ((w0.x + w0.y) + (w0.z + w0.w))
                 + ((w1.x + w1.y) + (w1.z + w1.w))
                 + ((w2.x + w2.y) + (w2.z + w2.w))
                 + ((w3.x + w3.y) + (w3.z + w3.w));
        }
        float actf = (node == node_prev) ? wsum : s_actf[node];
        if (t == 0 && node_prev >= 0) s_actf[node_prev] = wsum;

        float na;
        {
            float a = actf + s_actmsg + actb;
            float cand = 1.0f / (1.0f + expf(-a));
            na = (ta + cand > 1.0f) ? (1.0f - ta) : cand;
        }
        if (t == 0) s_tact[node] = ta + na;

        // ---- EXACT next-entry scan (warps 0-3): na known -> substitute ----
        int nfound = 0, nn = 0, nmid = 0;
        float xnext = 0.f, fnext = 0.f, mnext = 0.f;
        if (warp < 4) {
            int fp, fk; float ft;
            scan_q(s_qpack, s_tact, pos + 1, limit, lane,
                   node, ta + na, nfound, fp, fk, ft);
            if (nfound) {
                nn = fk & 1023; nmid = fk >> 10;
                if (nn != node) {                      // safe: row not written yet
                    xnext = g_feats[nn * Hh + t];
                    fnext = g_final[nn * Hh + t];
                }
                if (nmid != mid)
                    mnext = g_msgs[(size_t)nmid * Mm + t];
            }
            if (t == 0) {
                s_next[0] = nfound ? fp : (pos + 1);   // resume point on failure
                s_next[1] = fk;
                s_next[2] = __float_as_int(ft);
                s_next[3] = nfound;
            }
        }

        // ---- phase 2: ns matvec (register weights) ----
        {
            const unsigned long long* xp = (const unsigned long long*)xs;
            unsigned long long a0 = 0ull, a1 = 0ull;
#pragma unroll
            for (int kk = 0; kk < 8; kk++) {
                a0 = fma2(xp[c * 16 + 2 * kk],     wA[2 * kk],     a0);
                a1 = fma2(xp[c * 16 + 2 * kk + 1], wA[2 * kk + 1], a1);
            }
            float ax, ay, bx, by;
            unpack2(a0, ax, ay); unpack2(a1, bx, by);
            ax += bx; ay += by;
            ax += __shfl_xor_sync(FULL, ax, 8);
            ay += __shfl_xor_sync(FULL, ay, 8);
            ax += __shfl_xor_sync(FULL, ax, 16);
            ay += __shfl_xor_sync(FULL, ay, 16);
            if (c == 0) {
                float s = ax + ay + s_nsb[o] + s_nsmsg[o];
                float nsv = fmaxf(s, 0.0f);
                ys[o] = nsv;
                g_feats[node * Hh + o] = nsv;
                g_final[node * Hh + o] = s_fin[o] + nsv * na;
                // actf partial for this node -> write parity buffer pp^1
                float pw = nsv * s_actw[o];
                pw += __shfl_xor_sync(0x000000ffu, pw, 4);
                pw += __shfl_xor_sync(0x000000ffu, pw, 2);
                pw += __shfl_xor_sync(0x000000ffu, pw, 1);
                if (lane == 0) s_wtmp[pp ^ 1][warp] = pw;
            }
        }
        __syncthreads();   // sync2: ys/s_next ready; tact/feats/final visible

        // ---- phase 3: pick up next state, nm matvec, commit, enqueue ----
        const int npos  = s_next[0];
        const int npk   = s_next[1];
        const float nta = __int_as_float(s_next[2]);
        const int nhave = s_next[3];

        const int newmid = NSMAX + nproc;
        {
            const unsigned long long* yp = (const unsigned long long*)ys;
            unsigned long long a0 = 0ull, a1 = 0ull;
#pragma unroll
            for (int kk = 0; kk < 8; kk++) {
                a0 = fma2(yp[c * 16 + 2 * kk],     wB[2 * kk],     a0);
                a1 = fma2(yp[c * 16 + 2 * kk + 1], wB[2 * kk + 1], a1);
            }
            float ax, ay, bx, by;
            unpack2(a0, ax, ay); unpack2(a1, bx, by);
            ax += bx; ay += by;
            ax += __shfl_xor_sync(FULL, ax, 8);
            ay += __shfl_xor_sync(FULL, ay, 8);
            ax += __shfl_xor_sync(FULL, ax, 16);
            ay += __shfl_xor_sync(FULL, ay, 16);
            if (c == 0) {
                float s = ax + ay + s_nmb[o] + s_nmmsg[o];
                g_msgs[(size_t)newmid * Mm + o] = s;   // store message ONCE
            }
        }
        if (warp == 4 && lane < DEGk) {                // enqueue 16 entries
            int slot = tail + lane;
            if (slot < MAXD) s_qpack[slot] = (newmid << 10) | mynb;
        }
        if (warp < 4 && nfound) {                      // commit next-entry rows
            bool same = (nn == node);
            xs[t]    = same ? ys[t] : xnext;           // ys == new feats row
            s_fin[t] = same ? (s_fin[t] + ys[t] * na)  // == value stored to g_final
                            : fnext;
            if (nmid != mid) s_msg[t] = mnext;
        }

        node_prev = node;
        tail += DEGk;
        nproc += 1;
        pp ^= 1;
        pos = npos; pk = npk; ta = nta; have = nhave;
        __syncthreads();   // sync3: all state visible for next iteration
    }
}

// ---------------------------------------------------------------------------
// Kernel 3: readout.  g = sum_n final; logits = g . dec_w + dec_b; log_softmax
// ---------------------------------------------------------------------------
__global__ void k_readout(const float* __restrict__ dec_w,
                          const float* __restrict__ dec_b,
                          float* __restrict__ out)
{
    __shared__ float sg[Hh];
    __shared__ float sl[Pp * OUTn];
    int t = threadIdx.x;

    float acc = 0.0f;
#pragma unroll 4
    for (int n = 0; n < Nn; n++) acc += g_final[n * Hh + t];
    sg[t] = acc;
    __syncthreads();

    if (t < Pp * OUTn) {
        int p = t / OUTn, o = t - p * OUTn;
        float a = dec_b[t];
#pragma unroll 4
        for (int h = 0; h < Hh; h++)
            a += sg[h] * dec_w[(p * Hh + h) * OUTn + o];
        sl[t] = a;
    }
    __syncthreads();

    if (t < Pp) {
        float mx = -1e30f;
        for (int o = 0; o < OUTn; o++) mx = fmaxf(mx, sl[t * OUTn + o]);
        float s = 0.0f;
        for (int o = 0; o < OUTn; o++) s += expf(sl[t * OUTn + o] - mx);
        float lse = mx + logf(s);
        for (int o = 0; o < OUTn; o++)
            out[t * OUTn + o] = sl[t * OUTn + o] - lse;
    }
}

// ---------------------------------------------------------------------------
extern "C" void kernel_launch(void* const* d_in, const int* in_sizes, int n_in,
                              void* d_out, int out_size)
{
    int off = (n_in >= 14) ? 1 : 0;
    const float* xa        = (const float*)d_in[0];
    const float* fmsg      = (const float*)d_in[1];
    const int*   neighbors = (const int*)  d_in[2];
    const int*   nstart    = off ? (const int*)d_in[3] : nullptr;
    const float* enc_w = (const float*)d_in[3 + off];
    const float* enc_b = (const float*)d_in[4 + off];
    const float* ns_w  = (const float*)d_in[5 + off];
    const float* ns_b  = (const float*)d_in[6 + off];
    const float* nm_w  = (const float*)d_in[7 + off];
    const float* nm_b  = (const float*)d_in[8 + off];
    const float* act_w = (const float*)d_in[9 + off];
    const float* act_b = (const float*)d_in[10 + off];
    const float* dec_w = (const float*)d_in[11 + off];
    const float* dec_b = (const float*)d_in[12 + off];

    // dyn smem: 128 KB msg-half weights + 40 KB packed queue
    static const size_t DYN = 2 * 128 * 128 * sizeof(float) + MAXD * sizeof(int);
    cudaFuncSetAttribute(k_main, cudaFuncAttributeMaxDynamicSharedMemorySize,
                         (int)DYN);

    k_init<<<Nn, Hh>>>(xa, fmsg, nstart, enc_w, enc_b, act_w);
    k_main<<<1, 512, DYN>>>(neighbors, nstart, ns_w, ns_b, nm_w, nm_b,
                            act_w, act_b);
    k_readout<<<1, Hh>>>(dec_w, dec_b, (float*)d_out);
}